// round 2
// baseline (speedup 1.0000x reference)
#include <cuda_runtime.h>

#define NV   1024
#define NH   16384
#define NM   16384
#define NH4  (NH/4)
#define ROW4 ((NH+NM)/4)   // 8192 float4 per output row

// -------- device scratch (no allocations allowed) --------
__device__ float4 g_energy[NV];   // e_low, e_mid, e_high, total_before
__device__ float4 g_mult[NV];     // g_low, g_mid, g_high, noise_mult

// -------- per-voice band-energy reduction --------
__device__ __forceinline__ void acc_elem(float x, float f, float& e0, float& e1, float& e2, float& tot) {
    tot += x;
    if (f < 500.0f)       e0 += x;
    else if (f < 2000.0f) e1 += x;
    else                  e2 += x;
}

__global__ void __launch_bounds__(256) reduce_kernel(const float* __restrict__ harm,
                                                     const float* __restrict__ f0_hz) {
    const int v = blockIdx.x;
    const float f0 = f0_hz[v];
    const float4* row = reinterpret_cast<const float4*>(harm) + (size_t)v * NH4;

    float e0 = 0.f, e1 = 0.f, e2 = 0.f, tot = 0.f;
    for (int i = threadIdx.x; i < NH4; i += 256) {
        float4 x = row[i];
        const int h = 4 * i + 1;
        acc_elem(x.x, f0 * (float)(h),     e0, e1, e2, tot);
        acc_elem(x.y, f0 * (float)(h + 1), e0, e1, e2, tot);
        acc_elem(x.z, f0 * (float)(h + 2), e0, e1, e2, tot);
        acc_elem(x.w, f0 * (float)(h + 3), e0, e1, e2, tot);
    }

    const unsigned m = 0xFFFFFFFFu;
    #pragma unroll
    for (int o = 16; o; o >>= 1) {
        e0  += __shfl_down_sync(m, e0, o);
        e1  += __shfl_down_sync(m, e1, o);
        e2  += __shfl_down_sync(m, e2, o);
        tot += __shfl_down_sync(m, tot, o);
    }
    __shared__ float4 swp[8];
    const int lane = threadIdx.x & 31, wid = threadIdx.x >> 5;
    if (lane == 0) swp[wid] = make_float4(e0, e1, e2, tot);
    __syncthreads();
    if (wid == 0) {
        float4 a = (lane < 8) ? swp[lane] : make_float4(0.f, 0.f, 0.f, 0.f);
        #pragma unroll
        for (int o = 4; o; o >>= 1) {
            a.x += __shfl_down_sync(m, a.x, o);
            a.y += __shfl_down_sync(m, a.y, o);
            a.z += __shfl_down_sync(m, a.z, o);
            a.w += __shfl_down_sync(m, a.w, o);
        }
        if (lane == 0) g_energy[v] = a;
    }
}

// -------- per-voice gain computation (single block, 1024 threads) --------
// Also detects the is_active serialization in-kernel:
//   int32 mode:  words in {0, 1}
//   float32 mode: words in {0, 0x3F800000}
//   uint8 mode:  4 packed 0/1 bytes per word -> words >1 that aren't 1.0f
__global__ void __launch_bounds__(1024) voice_kernel(const unsigned int* __restrict__ isa,
                                                     const float* __restrict__ cw,
                                                     const float* __restrict__ wdr) {
    const int v = threadIdx.x;
    const unsigned m = 0xFFFFFFFFu;
    __shared__ unsigned int s_bytemode;

    // ---- encoding detection (threads 0..255 cover all encodings' first 1024 bytes) ----
    if (v == 0) s_bytemode = 0u;
    __syncthreads();
    if (v < 256) {
        unsigned int w = isa[v];
        bool weird = (w > 1u) && (w != 0x3F800000u);
        unsigned int any = __ballot_sync(m, weird);
        if (any && ((v & 31) == 0)) atomicOr(&s_bytemode, 1u);
    }
    __syncthreads();
    const bool bmode = (s_bytemode != 0u);

    const float4 e = g_energy[v];
    const bool active = bmode ? (reinterpret_cast<const unsigned char*>(isa)[v] != 0)
                              : (isa[v] != 0u);
    const float actf = active ? 1.0f : 0.0f;
    const float w = cw[v];

    // reduce: total_energy[3] (post-actf), total_weight, n_active
    float r0 = e.x * actf, r1 = e.y * actf, r2 = e.z * actf, r3 = w * actf, r4 = actf;
    #pragma unroll
    for (int o = 16; o; o >>= 1) {
        r0 += __shfl_down_sync(m, r0, o);
        r1 += __shfl_down_sync(m, r1, o);
        r2 += __shfl_down_sync(m, r2, o);
        r3 += __shfl_down_sync(m, r3, o);
        r4 += __shfl_down_sync(m, r4, o);
    }
    __shared__ float sred[32][5];
    __shared__ float tot[5];
    const int lane = v & 31, wid = v >> 5;
    if (lane == 0) {
        sred[wid][0] = r0; sred[wid][1] = r1; sred[wid][2] = r2;
        sred[wid][3] = r3; sred[wid][4] = r4;
    }
    __syncthreads();
    if (wid == 0) {
        float a0 = sred[lane][0], a1 = sred[lane][1], a2 = sred[lane][2];
        float a3 = sred[lane][3], a4 = sred[lane][4];
        #pragma unroll
        for (int o = 16; o; o >>= 1) {
            a0 += __shfl_down_sync(m, a0, o);
            a1 += __shfl_down_sync(m, a1, o);
            a2 += __shfl_down_sync(m, a2, o);
            a3 += __shfl_down_sync(m, a3, o);
            a4 += __shfl_down_sync(m, a4, o);
        }
        if (lane == 0) { tot[0]=a0; tot[1]=a1; tot[2]=a2; tot[3]=a3; tot[4]=a4; }
    }
    __syncthreads();

    const float TE[3] = { tot[0], tot[1], tot[2] };
    const float TW = fmaxf(tot[3], 1e-6f);
    const bool changed = (tot[4] >= 1.5f);   // n_active >= 2

    const float my_share = (w / TW) * 0.5f;  // claim_ratio * ENERGY_THRESHOLD
    const float en[3] = { e.x * actf, e.y * actf, e.z * actf };

    float g[3];
    #pragma unroll
    for (int b = 0; b < 3; ++b) {
        const float ex  = en[b] - my_share;
        const float er  = ex / fmaxf(en[b], 1e-6f);
        const float red = fmaxf(0.3f, 1.0f - wdr[3 * v + b] * er * 0.5f);
        const bool apply = (TE[b] > 0.5f) && (en[b] > 0.0f) && (ex > 0.0f) && active;
        g[b] = apply ? red : 1.0f;
    }

    const float total_after  = g[0] * en[0] + g[1] * en[1] + g[2] * en[2];
    const float total_before = e.w;
    const float ns = (total_before > 1e-6f) ? (total_after / total_before) : 1.0f;

    float4 mult;
    mult.x = changed ? g[0] : 1.0f;
    mult.y = changed ? g[1] : 1.0f;
    mult.z = changed ? g[2] : 1.0f;
    mult.w = (changed && active) ? ns : 1.0f;
    g_mult[v] = mult;
}

// -------- elementwise apply: out[v, 0:NH]=harm*g[band], out[v, NH:NH+NM]=noise*ns --------
__global__ void __launch_bounds__(256) apply_kernel(const float* __restrict__ harm,
                                                    const float* __restrict__ noise,
                                                    const float* __restrict__ f0_hz,
                                                    float* __restrict__ out) {
    const int v  = blockIdx.y;
    const int c4 = blockIdx.x * 256 + threadIdx.x;   // 0..ROW4-1
    const float4 g = g_mult[v];
    float4 o;
    if (c4 < NH4) {
        const float f0 = f0_hz[v];
        const float4 x = reinterpret_cast<const float4*>(harm)[(size_t)v * NH4 + c4];
        const int h = 4 * c4 + 1;
        float f;
        f = f0 * (float)(h);     o.x = x.x * (f < 500.f ? g.x : (f < 2000.f ? g.y : g.z));
        f = f0 * (float)(h + 1); o.y = x.y * (f < 500.f ? g.x : (f < 2000.f ? g.y : g.z));
        f = f0 * (float)(h + 2); o.z = x.z * (f < 500.f ? g.x : (f < 2000.f ? g.y : g.z));
        f = f0 * (float)(h + 3); o.w = x.w * (f < 500.f ? g.x : (f < 2000.f ? g.y : g.z));
    } else {
        const float4 x = reinterpret_cast<const float4*>(noise)[(size_t)v * NH4 + (c4 - NH4)];
        o.x = x.x * g.w; o.y = x.y * g.w; o.z = x.z * g.w; o.w = x.w * g.w;
    }
    reinterpret_cast<float4*>(out)[(size_t)v * ROW4 + c4] = o;
}

extern "C" void kernel_launch(void* const* d_in, const int* in_sizes, int n_in,
                              void* d_out, int out_size) {
    const float*        harm  = (const float*)d_in[0];
    const float*        noise = (const float*)d_in[1];
    const float*        f0    = (const float*)d_in[2];
    const float*        cw    = (const float*)d_in[3];
    const float*        wdr   = (const float*)d_in[4];
    const unsigned int* isa   = (const unsigned int*)d_in[5];
    float*              out   = (float*)d_out;

    reduce_kernel<<<NV, 256>>>(harm, f0);
    voice_kernel<<<1, 1024>>>(isa, cw, wdr);
    dim3 grid(ROW4 / 256, NV);
    apply_kernel<<<grid, 256>>>(harm, noise, f0, out);
}

// round 5
// speedup vs baseline: 1.0216x; 1.0216x over previous
#include <cuda_runtime.h>

#define NV   1024
#define NH   16384
#define NM   16384
#define NH4  (NH/4)
#define ROW4 ((NH+NM)/4)   // 8192 float4 per output row

// -------- device scratch (no allocations allowed) --------
__device__ float4 g_energy[NV];   // e_low, e_mid, e_high, total_before
__device__ float4 g_mult[NV];     // g_low, g_mid, g_high, noise_mult
__device__ int2   g_bounds[NV];   // k1 = max h with f<500, k2 = max h with f<2000

// -------- per-voice band-energy reduction --------
// Bands live entirely in h <= 64 (f0 >= 50 -> h >= 41 is always high band).
// Threads i<16 (h in 1..64) classify exactly; all other elements go to e2.
__global__ void __launch_bounds__(256) reduce_kernel(const float* __restrict__ harm,
                                                     const float* __restrict__ f0_hz) {
    const int v   = blockIdx.x;
    const int tid = threadIdx.x;
    const float f0 = f0_hz[v];   // uniform, L1-broadcast
    const float4* row = reinterpret_cast<const float4*>(harm) + (size_t)v * NH4;

    float e0 = 0.f, e1 = 0.f;
    float a0 = 0.f, a1 = 0.f, a2 = 0.f, a3 = 0.f;   // high-band bulk accumulators

    // iteration 0: head (classification for tid<16), bulk otherwise
    {
        float4 x = row[tid];
        if (tid < 16) {
            const int h = 4 * tid + 1;
            float f;
            f = f0 * (float)(h);     if (f < 500.f) e0 += x.x; else if (f < 2000.f) e1 += x.x; else a0 += x.x;
            f = f0 * (float)(h + 1); if (f < 500.f) e0 += x.y; else if (f < 2000.f) e1 += x.y; else a1 += x.y;
            f = f0 * (float)(h + 2); if (f < 500.f) e0 += x.z; else if (f < 2000.f) e1 += x.z; else a2 += x.z;
            f = f0 * (float)(h + 3); if (f < 500.f) e0 += x.w; else if (f < 2000.f) e1 += x.w; else a3 += x.w;
        } else {
            a0 += x.x; a1 += x.y; a2 += x.z; a3 += x.w;
        }
    }
    // iterations 1..15: pure streaming sum (all guaranteed high band)
    #pragma unroll
    for (int it = 1; it < 16; ++it) {
        float4 x = row[tid + it * 256];
        a0 += x.x; a1 += x.y; a2 += x.z; a3 += x.w;
    }
    float e2 = (a0 + a1) + (a2 + a3);

    // block reduction of (e0, e1, e2)
    const unsigned m = 0xFFFFFFFFu;
    #pragma unroll
    for (int o = 16; o; o >>= 1) {
        e0 += __shfl_down_sync(m, e0, o);
        e1 += __shfl_down_sync(m, e1, o);
        e2 += __shfl_down_sync(m, e2, o);
    }
    __shared__ float3 swp[8];
    const int lane = tid & 31, wid = tid >> 5;
    if (lane == 0) swp[wid] = make_float3(e0, e1, e2);
    __syncthreads();
    if (wid == 0) {
        float3 a = (lane < 8) ? swp[lane] : make_float3(0.f, 0.f, 0.f);
        #pragma unroll
        for (int o = 4; o; o >>= 1) {
            a.x += __shfl_down_sync(m, a.x, o);
            a.y += __shfl_down_sync(m, a.y, o);
            a.z += __shfl_down_sync(m, a.z, o);
        }
        if (lane == 0) g_energy[v] = make_float4(a.x, a.y, a.z, a.x + a.y + a.z);
    }
}

// -------- per-voice gain computation (single block, 1024 threads) --------
// Also detects the is_active serialization in-kernel:
//   int32 mode:  words in {0, 1}
//   float32 mode: words in {0, 0x3F800000}
//   uint8 mode:  4 packed 0/1 bytes per word -> words >1 that aren't 1.0f
__global__ void __launch_bounds__(1024) voice_kernel(const unsigned int* __restrict__ isa,
                                                     const float* __restrict__ cw,
                                                     const float* __restrict__ wdr,
                                                     const float* __restrict__ f0_hz) {
    const int v = threadIdx.x;
    const unsigned m = 0xFFFFFFFFu;
    __shared__ unsigned int s_bytemode;

    if (v == 0) s_bytemode = 0u;
    __syncthreads();
    if (v < 256) {
        unsigned int w = isa[v];
        bool weird = (w > 1u) && (w != 0x3F800000u);
        unsigned int any = __ballot_sync(m, weird);
        if (any && ((v & 31) == 0)) atomicOr(&s_bytemode, 1u);
    }
    __syncthreads();
    const bool bmode = (s_bytemode != 0u);

    // exact integer band boundaries for this voice (bands end by h=64)
    {
        const float f0 = f0_hz[v];
        int k1 = 0, k2 = 0;
        #pragma unroll
        for (int h = 1; h <= 64; ++h) {
            float f = f0 * (float)h;
            if (f < 500.f)  ++k1;
            if (f < 2000.f) ++k2;
        }
        g_bounds[v] = make_int2(k1, k2);
    }

    const float4 e = g_energy[v];
    const bool active = bmode ? (reinterpret_cast<const unsigned char*>(isa)[v] != 0)
                              : (isa[v] != 0u);
    const float actf = active ? 1.0f : 0.0f;
    const float w = cw[v];

    // reduce: total_energy[3] (post-actf), total_weight, n_active
    float r0 = e.x * actf, r1 = e.y * actf, r2 = e.z * actf, r3 = w * actf, r4 = actf;
    #pragma unroll
    for (int o = 16; o; o >>= 1) {
        r0 += __shfl_down_sync(m, r0, o);
        r1 += __shfl_down_sync(m, r1, o);
        r2 += __shfl_down_sync(m, r2, o);
        r3 += __shfl_down_sync(m, r3, o);
        r4 += __shfl_down_sync(m, r4, o);
    }
    __shared__ float sred[32][5];
    __shared__ float tot[5];
    const int lane = v & 31, wid = v >> 5;
    if (lane == 0) {
        sred[wid][0] = r0; sred[wid][1] = r1; sred[wid][2] = r2;
        sred[wid][3] = r3; sred[wid][4] = r4;
    }
    __syncthreads();
    if (wid == 0) {
        float a0 = sred[lane][0], a1 = sred[lane][1], a2 = sred[lane][2];
        float a3 = sred[lane][3], a4 = sred[lane][4];
        #pragma unroll
        for (int o = 16; o; o >>= 1) {
            a0 += __shfl_down_sync(m, a0, o);
            a1 += __shfl_down_sync(m, a1, o);
            a2 += __shfl_down_sync(m, a2, o);
            a3 += __shfl_down_sync(m, a3, o);
            a4 += __shfl_down_sync(m, a4, o);
        }
        if (lane == 0) { tot[0]=a0; tot[1]=a1; tot[2]=a2; tot[3]=a3; tot[4]=a4; }
    }
    __syncthreads();

    const float TE[3] = { tot[0], tot[1], tot[2] };
    const float TW = fmaxf(tot[3], 1e-6f);
    const bool changed = (tot[4] >= 1.5f);   // n_active >= 2

    const float my_share = (w / TW) * 0.5f;  // claim_ratio * ENERGY_THRESHOLD
    const float en[3] = { e.x * actf, e.y * actf, e.z * actf };

    float g[3];
    #pragma unroll
    for (int b = 0; b < 3; ++b) {
        const float ex  = en[b] - my_share;
        const float er  = ex / fmaxf(en[b], 1e-6f);
        const float red = fmaxf(0.3f, 1.0f - wdr[3 * v + b] * er * 0.5f);
        const bool apply = (TE[b] > 0.5f) && (en[b] > 0.0f) && (ex > 0.0f) && active;
        g[b] = apply ? red : 1.0f;
    }

    const float total_after  = g[0] * e.x + g[1] * e.y + g[2] * e.z;
    const float total_before = e.w;
    const float ns = (total_before > 1e-6f) ? (total_after / total_before) : 1.0f;

    float4 mult;
    mult.x = changed ? g[0] : 1.0f;
    mult.y = changed ? g[1] : 1.0f;
    mult.z = changed ? g[2] : 1.0f;
    mult.w = (changed && active) ? ns : 1.0f;
    g_mult[v] = mult;
}

// -------- elementwise apply, uniform-branched on blockIdx.x --------
//   block 0      : harm, h in [1,1024] -> integer band select via g_bounds
//   blocks 1..15 : harm, guaranteed high band -> * g.z
//   blocks 16..31: noise -> * g.w
__global__ void __launch_bounds__(256) apply_kernel(const float* __restrict__ harm,
                                                    const float* __restrict__ noise,
                                                    float* __restrict__ out) {
    const int v  = blockIdx.y;
    const int bx = blockIdx.x;
    const int c4 = bx * 256 + threadIdx.x;
    const float4 g = g_mult[v];
    float4 o;
    if (bx >= 16) {
        const float4 x = reinterpret_cast<const float4*>(noise)[(size_t)v * NH4 + (c4 - NH4)];
        o.x = x.x * g.w; o.y = x.y * g.w; o.z = x.z * g.w; o.w = x.w * g.w;
    } else if (bx >= 1) {
        const float4 x = reinterpret_cast<const float4*>(harm)[(size_t)v * NH4 + c4];
        o.x = x.x * g.z; o.y = x.y * g.z; o.z = x.z * g.z; o.w = x.w * g.z;
    } else {
        const int2 kb = g_bounds[v];
        const float4 x = reinterpret_cast<const float4*>(harm)[(size_t)v * NH4 + c4];
        const int h = 4 * c4 + 1;
        o.x = x.x * ((h    ) <= kb.x ? g.x : ((h    ) <= kb.y ? g.y : g.z));
        o.y = x.y * ((h + 1) <= kb.x ? g.x : ((h + 1) <= kb.y ? g.y : g.z));
        o.z = x.z * ((h + 2) <= kb.x ? g.x : ((h + 2) <= kb.y ? g.y : g.z));
        o.w = x.w * ((h + 3) <= kb.x ? g.x : ((h + 3) <= kb.y ? g.y : g.z));
    }
    reinterpret_cast<float4*>(out)[(size_t)v * ROW4 + c4] = o;
}

extern "C" void kernel_launch(void* const* d_in, const int* in_sizes, int n_in,
                              void* d_out, int out_size) {
    const float*        harm  = (const float*)d_in[0];
    const float*        noise = (const float*)d_in[1];
    const float*        f0    = (const float*)d_in[2];
    const float*        cw    = (const float*)d_in[3];
    const float*        wdr   = (const float*)d_in[4];
    const unsigned int* isa   = (const unsigned int*)d_in[5];
    float*              out   = (float*)d_out;

    reduce_kernel<<<NV, 256>>>(harm, f0);
    voice_kernel<<<1, 1024>>>(isa, cw, wdr, f0);
    dim3 grid(ROW4 / 256, NV);
    apply_kernel<<<grid, 256>>>(harm, noise, out);
}

// round 8
// speedup vs baseline: 1.0267x; 1.0050x over previous
#include <cuda_runtime.h>

#define NV   1024
#define NH   16384
#define NM   16384
#define NH4  (NH/4)        // 4096 float4 harm per row
#define ROW4 ((NH+NM)/4)   // 8192 float4 per output row

// -------- device scratch (no allocations allowed) --------
__device__ float4 g_energy[NV];   // e_low, e_mid, e_high, total_before
__device__ float4 g_mult[NV];     // g_low, g_mid, g_high, noise_mult
__device__ int2   g_bounds[NV];   // k1 = max h with f<500, k2 = max h with f<2000

__device__ __forceinline__ void stcs4(float4* p, float4 v) {
    asm volatile("st.global.cs.v4.f32 [%0], {%1,%2,%3,%4};"
                 :: "l"(p), "f"(v.x), "f"(v.y), "f"(v.z), "f"(v.w) : "memory");
}
__device__ __forceinline__ float4 ldcs4(const float4* p) {
    float4 v;
    asm volatile("ld.global.cs.v4.f32 {%0,%1,%2,%3}, [%4];"
                 : "=f"(v.x), "=f"(v.y), "=f"(v.z), "=f"(v.w) : "l"(p));
    return v;
}

// -------- per-voice band-energy reduction --------
// Bands live entirely in h <= 64 (f0 >= 50 -> h >= 41 is always high band).
// Threads tid<16 (h in 1..64) classify exactly; all other elements go to e2.
__global__ void __launch_bounds__(512) reduce_kernel(const float* __restrict__ harm,
                                                     const float* __restrict__ f0_hz) {
    const int v   = blockIdx.x;
    const int tid = threadIdx.x;
    const float f0 = f0_hz[v];   // uniform, L1-broadcast
    const float4* row = reinterpret_cast<const float4*>(harm) + (size_t)v * NH4;

    float e0 = 0.f, e1 = 0.f;
    float a0 = 0.f, a1 = 0.f, a2 = 0.f, a3 = 0.f;   // high-band bulk accumulators

    // iteration 0: head (classification for tid<16), bulk otherwise
    {
        float4 x = row[tid];
        if (tid < 16) {
            const int h = 4 * tid + 1;
            float f;
            f = f0 * (float)(h);     if (f < 500.f) e0 += x.x; else if (f < 2000.f) e1 += x.x; else a0 += x.x;
            f = f0 * (float)(h + 1); if (f < 500.f) e0 += x.y; else if (f < 2000.f) e1 += x.y; else a1 += x.y;
            f = f0 * (float)(h + 2); if (f < 500.f) e0 += x.z; else if (f < 2000.f) e1 += x.z; else a2 += x.z;
            f = f0 * (float)(h + 3); if (f < 500.f) e0 += x.w; else if (f < 2000.f) e1 += x.w; else a3 += x.w;
        } else {
            a0 += x.x; a1 += x.y; a2 += x.z; a3 += x.w;
        }
    }
    // iterations 1..7: pure streaming sum (all guaranteed high band)
    #pragma unroll
    for (int it = 1; it < 8; ++it) {
        float4 x = row[tid + it * 512];
        a0 += x.x; a1 += x.y; a2 += x.z; a3 += x.w;
    }
    float e2 = (a0 + a1) + (a2 + a3);

    // block reduction of (e0, e1, e2)
    const unsigned m = 0xFFFFFFFFu;
    #pragma unroll
    for (int o = 16; o; o >>= 1) {
        e0 += __shfl_down_sync(m, e0, o);
        e1 += __shfl_down_sync(m, e1, o);
        e2 += __shfl_down_sync(m, e2, o);
    }
    __shared__ float3 swp[16];
    const int lane = tid & 31, wid = tid >> 5;
    if (lane == 0) swp[wid] = make_float3(e0, e1, e2);
    __syncthreads();
    if (wid == 0) {
        float3 a = (lane < 16) ? swp[lane] : make_float3(0.f, 0.f, 0.f);
        #pragma unroll
        for (int o = 8; o; o >>= 1) {
            a.x += __shfl_down_sync(m, a.x, o);
            a.y += __shfl_down_sync(m, a.y, o);
            a.z += __shfl_down_sync(m, a.z, o);
        }
        if (lane == 0) g_energy[v] = make_float4(a.x, a.y, a.z, a.x + a.y + a.z);
    }
}

// -------- per-voice gain computation (single block, 1024 threads) --------
// Also detects the is_active serialization in-kernel:
//   int32 mode:  words in {0, 1}
//   float32 mode: words in {0, 0x3F800000}
//   uint8 mode:  4 packed 0/1 bytes per word -> words >1 that aren't 1.0f
__global__ void __launch_bounds__(1024) voice_kernel(const unsigned int* __restrict__ isa,
                                                     const float* __restrict__ cw,
                                                     const float* __restrict__ wdr,
                                                     const float* __restrict__ f0_hz) {
    const int v = threadIdx.x;
    const unsigned m = 0xFFFFFFFFu;
    __shared__ unsigned int s_bytemode;

    if (v == 0) s_bytemode = 0u;
    __syncthreads();
    if (v < 256) {
        unsigned int w = isa[v];
        bool weird = (w > 1u) && (w != 0x3F800000u);
        unsigned int any = __ballot_sync(m, weird);
        if (any && ((v & 31) == 0)) atomicOr(&s_bytemode, 1u);
    }
    __syncthreads();
    const bool bmode = (s_bytemode != 0u);

    // exact integer band boundaries for this voice (bands end by h=64)
    {
        const float f0 = f0_hz[v];
        int k1 = 0, k2 = 0;
        #pragma unroll
        for (int h = 1; h <= 64; ++h) {
            float f = f0 * (float)h;
            if (f < 500.f)  ++k1;
            if (f < 2000.f) ++k2;
        }
        g_bounds[v] = make_int2(k1, k2);
    }

    const float4 e = g_energy[v];
    const bool active = bmode ? (reinterpret_cast<const unsigned char*>(isa)[v] != 0)
                              : (isa[v] != 0u);
    const float actf = active ? 1.0f : 0.0f;
    const float w = cw[v];

    // reduce: total_energy[3] (post-actf), total_weight, n_active
    float r0 = e.x * actf, r1 = e.y * actf, r2 = e.z * actf, r3 = w * actf, r4 = actf;
    #pragma unroll
    for (int o = 16; o; o >>= 1) {
        r0 += __shfl_down_sync(m, r0, o);
        r1 += __shfl_down_sync(m, r1, o);
        r2 += __shfl_down_sync(m, r2, o);
        r3 += __shfl_down_sync(m, r3, o);
        r4 += __shfl_down_sync(m, r4, o);
    }
    __shared__ float sred[32][5];
    __shared__ float tot[5];
    const int lane = v & 31, wid = v >> 5;
    if (lane == 0) {
        sred[wid][0] = r0; sred[wid][1] = r1; sred[wid][2] = r2;
        sred[wid][3] = r3; sred[wid][4] = r4;
    }
    __syncthreads();
    if (wid == 0) {
        float a0 = sred[lane][0], a1 = sred[lane][1], a2 = sred[lane][2];
        float a3 = sred[lane][3], a4 = sred[lane][4];
        #pragma unroll
        for (int o = 16; o; o >>= 1) {
            a0 += __shfl_down_sync(m, a0, o);
            a1 += __shfl_down_sync(m, a1, o);
            a2 += __shfl_down_sync(m, a2, o);
            a3 += __shfl_down_sync(m, a3, o);
            a4 += __shfl_down_sync(m, a4, o);
        }
        if (lane == 0) { tot[0]=a0; tot[1]=a1; tot[2]=a2; tot[3]=a3; tot[4]=a4; }
    }
    __syncthreads();

    const float TE[3] = { tot[0], tot[1], tot[2] };
    const float TW = fmaxf(tot[3], 1e-6f);
    const bool changed = (tot[4] >= 1.5f);   // n_active >= 2

    const float my_share = (w / TW) * 0.5f;  // claim_ratio * ENERGY_THRESHOLD
    const float en[3] = { e.x * actf, e.y * actf, e.z * actf };

    float g[3];
    #pragma unroll
    for (int b = 0; b < 3; ++b) {
        const float ex  = en[b] - my_share;
        const float er  = ex / fmaxf(en[b], 1e-6f);
        const float red = fmaxf(0.3f, 1.0f - wdr[3 * v + b] * er * 0.5f);
        const bool apply = (TE[b] > 0.5f) && (en[b] > 0.0f) && (ex > 0.0f) && active;
        g[b] = apply ? red : 1.0f;
    }

    const float total_after  = g[0] * e.x + g[1] * e.y + g[2] * e.z;
    const float total_before = e.w;
    const float ns = (total_before > 1e-6f) ? (total_after / total_before) : 1.0f;

    float4 mult;
    mult.x = changed ? g[0] : 1.0f;
    mult.y = changed ? g[1] : 1.0f;
    mult.z = changed ? g[2] : 1.0f;
    mult.w = (changed && active) ? ns : 1.0f;
    g_mult[v] = mult;
}

// -------- elementwise apply, 2048 float4 per block (256 thr x 8 unit-stride iters) --------
// block role = blockIdx.x & 3:
//   0    : harm c4 [0,2048)    — iter 0 uses integer band bounds, iters 1..7 high band
//   1    : harm c4 [2048,4096) — * g.z
//   2..3 : noise               — * g.w  (streaming loads)
__global__ void __launch_bounds__(256) apply_kernel(const float* __restrict__ harm,
                                                    const float* __restrict__ noise,
                                                    float* __restrict__ out) {
    const int b   = blockIdx.x;
    const int v   = b >> 2;
    const int bx  = b & 3;
    const int tid = threadIdx.x;
    const float4 g = g_mult[v];
    float4* dst = reinterpret_cast<float4*>(out) + (size_t)v * ROW4 + bx * 2048;

    if (bx >= 2) {
        const float4* src = reinterpret_cast<const float4*>(noise)
                          + ((size_t)v << 12) + (bx - 2) * 2048;
        const float s = g.w;
        #pragma unroll
        for (int i = 0; i < 8; ++i) {
            float4 x = ldcs4(src + tid + i * 256);
            stcs4(dst + tid + i * 256, make_float4(x.x * s, x.y * s, x.z * s, x.w * s));
        }
    } else if (bx == 1) {
        const float4* src = reinterpret_cast<const float4*>(harm) + ((size_t)v << 12) + 2048;
        const float s = g.z;
        #pragma unroll
        for (int i = 0; i < 8; ++i) {
            float4 x = src[tid + i * 256];
            stcs4(dst + tid + i * 256, make_float4(x.x * s, x.y * s, x.z * s, x.w * s));
        }
    } else {
        const float4* src = reinterpret_cast<const float4*>(harm) + ((size_t)v << 12);
        // iteration 0: c4 = tid in [0,256) -> integer band select via g_bounds
        {
            const int2 kb = g_bounds[v];
            float4 x = src[tid];
            const int h = 4 * tid + 1;
            float4 o;
            o.x = x.x * ((h    ) <= kb.x ? g.x : ((h    ) <= kb.y ? g.y : g.z));
            o.y = x.y * ((h + 1) <= kb.x ? g.x : ((h + 1) <= kb.y ? g.y : g.z));
            o.z = x.z * ((h + 2) <= kb.x ? g.x : ((h + 2) <= kb.y ? g.y : g.z));
            o.w = x.w * ((h + 3) <= kb.x ? g.x : ((h + 3) <= kb.y ? g.y : g.z));
            stcs4(dst + tid, o);
        }
        const float s = g.z;
        #pragma unroll
        for (int i = 1; i < 8; ++i) {
            float4 x = src[tid + i * 256];
            stcs4(dst + tid + i * 256, make_float4(x.x * s, x.y * s, x.z * s, x.w * s));
        }
    }
}

extern "C" void kernel_launch(void* const* d_in, const int* in_sizes, int n_in,
                              void* d_out, int out_size) {
    const float*        harm  = (const float*)d_in[0];
    const float*        noise = (const float*)d_in[1];
    const float*        f0    = (const float*)d_in[2];
    const float*        cw    = (const float*)d_in[3];
    const float*        wdr   = (const float*)d_in[4];
    const unsigned int* isa   = (const unsigned int*)d_in[5];
    float*              out   = (float*)d_out;

    reduce_kernel<<<NV, 512>>>(harm, f0);
    voice_kernel<<<1, 1024>>>(isa, cw, wdr, f0);
    apply_kernel<<<NV * 4, 256>>>(harm, noise, out);
}